// round 15
// baseline (speedup 1.0000x reference)
#include <cuda_runtime.h>
#include <math.h>

// Problem constants (fixed by setup_inputs)
#define T   64
#define NS  75
#define NW  5
#define NN  375   // NS*NW
#define DD  4096
#define NQ  150
#define SIGMA_C 0.1f
#define CREG    0.1f
#define MAXIT   15

// ---------------- device scratch (no allocations allowed) ----------------
__device__ float g_K[T][NS][NS];          // Gram per task
__device__ float g_Kpart[4][T][NS][NS];   // split-K partials
__device__ float g_Minv[T][NW][NS][NS];   // per-way inverse of (K+I+diag(Dw))
__device__ float g_z[T][NN], g_s[T][NN], g_lam[T][NN];
__device__ float g_e[T][NN], g_h[T][NN];
__device__ float g_r1[T][NN], g_Dv[T][NN], g_rs[T][NN], g_u[T][NN];
__device__ float g_nu[T][NS], g_ra[T][NS];
__device__ float g_mu[T];
__device__ float g_W[T][NW][DD];

// ---------------- Gram: K[t] = S_t S_t^T, split-K over 4 chunks ----------------
__global__ __launch_bounds__(256) void gram_kernel(const float* __restrict__ sup) {
    int c = blockIdx.x, t = blockIdx.y;
    int k0base = c * 1024;
    __shared__ float As[16][80];
    int tx = threadIdx.x % 16, ty = threadIdx.x / 16;
    int kk = tx, rr = ty;
    float acc[5][5];
#pragma unroll
    for (int a = 0; a < 5; a++)
#pragma unroll
        for (int b = 0; b < 5; b++) acc[a][b] = 0.f;
    const float* Sp = sup + (size_t)t * NS * DD;
    for (int kt = 0; kt < 64; kt++) {
        int k0 = k0base + kt * 16;
        __syncthreads();
#pragma unroll
        for (int rb = 0; rb < 80; rb += 16) {
            int r = rb + rr;
            As[kk][r] = (r < NS) ? Sp[(size_t)r * DD + k0 + kk] : 0.f;
        }
        __syncthreads();
#pragma unroll
        for (int k = 0; k < 16; k++) {
            float a[5], b[5];
#pragma unroll
            for (int i = 0; i < 5; i++) a[i] = As[k][ty * 5 + i];
#pragma unroll
            for (int j = 0; j < 5; j++) b[j] = As[k][tx * 5 + j];
#pragma unroll
            for (int i = 0; i < 5; i++)
#pragma unroll
                for (int j = 0; j < 5; j++) acc[i][j] += a[i] * b[j];
        }
    }
#pragma unroll
    for (int i = 0; i < 5; i++) {
        int r = ty * 5 + i; if (r >= NS) continue;
#pragma unroll
        for (int j = 0; j < 5; j++) {
            int cc = tx * 5 + j; if (cc >= NS) continue;
            g_Kpart[c][t][r][cc] = acc[i][j];
        }
    }
}

__global__ void gram_reduce() {
    int idx = blockIdx.x * 256 + threadIdx.x;
    if (idx < T * NS * NS) {
        const float* p = (const float*)g_Kpart;
        float v = 0.f;
#pragma unroll
        for (int c = 0; c < 4; c++) v += p[c * T * NS * NS + idx];
        ((float*)g_K)[idx] = v;
    }
}

// ---------------- init state ----------------
__global__ void setup_kernel(const int* __restrict__ labels) {
    int t = blockIdx.x, tid = threadIdx.x;
    if (tid < NN) {
        int i = tid / NW, w = tid % NW;
        float y = (labels[t * NS + i] == w) ? 1.f : 0.f;
        g_e[t][tid] = -y;
        g_h[t][tid] = CREG * y;
        g_z[t][tid] = 0.f;
        g_s[t][tid] = 1.f;
        g_lam[t][tid] = 1.f;
    }
    if (tid < NS) g_nu[t][tid] = 0.f;
}

// ---------------- residuals: rz, rs, ra, mu, r1, D ----------------
__global__ __launch_bounds__(384) void resid_kernel() {
    int t = blockIdx.x, tid = threadIdx.x;
    __shared__ float Zs[NN];
    __shared__ float red[12];
    __shared__ float smu;
    float z = 0.f, s = 1.f, lam = 1.f, e = 0.f, h = 0.f;
    if (tid < NN) {
        z = g_z[t][tid]; Zs[tid] = z;
        s = g_s[t][tid]; lam = g_lam[t][tid];
        e = g_e[t][tid]; h = g_h[t][tid];
    }
    __syncthreads();
    // mu = mean(lam*s)
    float ls = (tid < NN) ? lam * s : 0.f;
#pragma unroll
    for (int o = 16; o > 0; o >>= 1) ls += __shfl_down_sync(0xffffffffu, ls, o);
    if ((tid & 31) == 0) red[tid >> 5] = ls;
    __syncthreads();
    if (tid == 0) {
        float sum = 0.f;
        for (int wi = 0; wi < 12; wi++) sum += red[wi];
        float mu = sum / (float)NN;
        g_mu[t] = mu; smu = mu;
    }
    __syncthreads();
    float mu = smu;
    if (tid < NN) {
        int i = tid / NW, w = tid % NW;
        const float* Krow = &g_K[t][i][0];
        float kz = 0.f;
        for (int j = 0; j < NS; j++) kz += Krow[j] * Zs[j * NW + w];
        float rz = kz + z + e + lam + g_nu[t][i];
        float rs = z + s - h;
        float r1 = -rz - (lam * rs - lam * s + SIGMA_C * mu) / s;
        g_rs[t][tid] = rs;
        g_r1[t][tid] = r1;
        g_Dv[t][tid] = lam / s;
    }
    if (tid < NS) {
        float ra = 0.f;
#pragma unroll
        for (int w = 0; w < NW; w++) ra += Zs[tid * NW + w];
        g_ra[t][tid] = ra;
    }
}

// ---------------- per (task,way): M = K+I+diag(Dw), Cholesky, invert, u = Minv*r1_w ----------------
__global__ __launch_bounds__(256) void factor_kernel() {
    int w = blockIdx.x, t = blockIdx.y, tid = threadIdx.x;
    __shared__ float M[NS][NS + 1];
    __shared__ float X[NS][NS + 1];
    __shared__ float r1w[NS];
    for (int idx = tid; idx < NS * NS; idx += 256) {
        int i = idx / NS, j = idx % NS;
        float v = g_K[t][i][j];
        if (i == j) v += 1.f + g_Dv[t][i * NW + w];
        M[i][j] = v;
        X[i][j] = (i == j) ? 1.f : 0.f;
    }
    for (int j = tid; j < NS; j += 256) r1w[j] = g_r1[t][j * NW + w];
    __syncthreads();
    // Cholesky (lower, in place)
    for (int k = 0; k < NS; k++) {
        if (tid == 0) M[k][k] = sqrtf(M[k][k]);
        __syncthreads();
        float invd = 1.f / M[k][k];
        for (int i = k + 1 + tid; i < NS; i += 256) M[i][k] *= invd;
        __syncthreads();
        int nr = NS - 1 - k;
        for (int idx = tid; idx < nr * nr; idx += 256) {
            int i = k + 1 + idx / nr, j = k + 1 + idx % nr;
            if (j <= i) M[i][j] -= M[i][k] * M[j][k];
        }
        __syncthreads();
    }
    // forward: L Y = I  (column sweep)
    for (int r = 0; r < NS; r++) {
        float invd = 1.f / M[r][r];
        for (int c = tid; c < NS; c += 256) X[r][c] *= invd;
        __syncthreads();
        int nr = NS - 1 - r;
        for (int idx = tid; idx < nr * NS; idx += 256) {
            int i = r + 1 + idx / NS, c = idx % NS;
            X[i][c] -= M[i][r] * X[r][c];
        }
        __syncthreads();
    }
    // backward: L^T X = Y
    for (int r = NS - 1; r >= 0; r--) {
        float invd = 1.f / M[r][r];
        for (int c = tid; c < NS; c += 256) X[r][c] *= invd;
        __syncthreads();
        for (int idx = tid; idx < r * NS; idx += 256) {
            int i = idx / NS, c = idx % NS;
            X[i][c] -= M[r][i] * X[r][c];
        }
        __syncthreads();
    }
    // write Minv + u
    for (int idx = tid; idx < NS * NS; idx += 256)
        g_Minv[t][w][idx / NS][idx % NS] = X[idx / NS][idx % NS];
    for (int i = tid; i < NS; i += 256) {
        float acc = 0.f;
        for (int j = 0; j < NS; j++) acc += X[i][j] * r1w[j];
        g_u[t][i * NW + w] = acc;
    }
}

// ---------------- per task: Schur solve for dnu, dz, step length, state update ----------------
__global__ __launch_bounds__(384) void schur_kernel() {
    int t = blockIdx.x, tid = threadIdx.x;
    __shared__ float S[NS][NS + 1];
    __shared__ float rhs[NS];
    __shared__ float us[NN];
    __shared__ float red[12];
    __shared__ float salpha;
    for (int idx = tid; idx < NS * NS; idx += 384) {
        int i = idx / NS, j = idx % NS;
        float acc = 0.f;
#pragma unroll
        for (int w = 0; w < NW; w++) acc += g_Minv[t][w][i][j];
        S[i][j] = acc;
    }
    if (tid < NN) us[tid] = g_u[t][tid];
    __syncthreads();
    if (tid < NS) {
        float acc = g_ra[t][tid];
#pragma unroll
        for (int w = 0; w < NW; w++) acc += us[tid * NW + w];
        rhs[tid] = acc;
    }
    __syncthreads();
    // Cholesky on S
    for (int k = 0; k < NS; k++) {
        if (tid == 0) S[k][k] = sqrtf(S[k][k]);
        __syncthreads();
        float invd = 1.f / S[k][k];
        for (int i = k + 1 + tid; i < NS; i += 384) S[i][k] *= invd;
        __syncthreads();
        int nr = NS - 1 - k;
        for (int idx = tid; idx < nr * nr; idx += 384) {
            int i = k + 1 + idx / nr, j = k + 1 + idx % nr;
            if (j <= i) S[i][j] -= S[i][k] * S[j][k];
        }
        __syncthreads();
    }
    // forward L y = rhs
    for (int r = 0; r < NS; r++) {
        if (tid == 0) rhs[r] /= S[r][r];
        __syncthreads();
        float yr = rhs[r];
        for (int i = r + 1 + tid; i < NS; i += 384) rhs[i] -= S[i][r] * yr;
        __syncthreads();
    }
    // backward L^T dnu = y
    for (int r = NS - 1; r >= 0; r--) {
        if (tid == 0) rhs[r] /= S[r][r];
        __syncthreads();
        float yr = rhs[r];
        for (int i = tid; i < r; i += 384) rhs[i] -= S[r][i] * yr;
        __syncthreads();
    }
    // rhs == dnu now. dz_w = u_w - Minv_w * dnu
    float dz = 0.f, ds = 0.f, dlam = 0.f, rat = INFINITY;
    float z = 0.f, s = 1.f, lam = 1.f;
    if (tid < NN) {
        int i = tid / NW, w = tid % NW;
        float acc = us[tid];
        const float* Mi = &g_Minv[t][w][i][0];
        for (int j = 0; j < NS; j++) acc -= Mi[j] * rhs[j];
        dz = acc;
        z = g_z[t][tid]; s = g_s[t][tid]; lam = g_lam[t][tid];
        float rsv = g_rs[t][tid];
        float mu = g_mu[t];
        ds = -rsv - dz;
        dlam = (lam * dz + lam * rsv - lam * s + SIGMA_C * mu) / s;
        float ra1 = (ds   < 0.f) ? (-s   / ds)   : INFINITY;
        float ra2 = (dlam < 0.f) ? (-lam / dlam) : INFINITY;
        rat = fminf(ra1, ra2);
    }
#pragma unroll
    for (int o = 16; o > 0; o >>= 1) rat = fminf(rat, __shfl_down_sync(0xffffffffu, rat, o));
    if ((tid & 31) == 0) red[tid >> 5] = rat;
    __syncthreads();
    if (tid == 0) {
        float m = red[0];
        for (int wi = 1; wi < 12; wi++) m = fminf(m, red[wi]);
        salpha = fminf(1.f, 0.99f * m);
    }
    __syncthreads();
    float alpha = salpha;
    if (tid < NN) {
        g_z[t][tid]   = z   + alpha * dz;
        g_s[t][tid]   = s   + alpha * ds;
        g_lam[t][tid] = lam + alpha * dlam;
    }
    if (tid < NS) g_nu[t][tid] += alpha * rhs[tid];
}

// ---------------- W[t,w,d] = sum_n sup[t,n,d] * z[t,n*NW+w] ----------------
__global__ __launch_bounds__(256) void wproj_kernel(const float* __restrict__ sup) {
    int t = blockIdx.y;
    int d = blockIdx.x * 256 + threadIdx.x;
    __shared__ float zs[NN];
    for (int idx = threadIdx.x; idx < NN; idx += 256) zs[idx] = g_z[t][idx];
    __syncthreads();
    float acc[NW] = {0.f, 0.f, 0.f, 0.f, 0.f};
    const float* Sp = sup + (size_t)t * NS * DD + d;
    for (int n = 0; n < NS; n++) {
        float sv = Sp[(size_t)n * DD];
#pragma unroll
        for (int w = 0; w < NW; w++) acc[w] += sv * zs[n * NW + w];
    }
#pragma unroll
    for (int w = 0; w < NW; w++) g_W[t][w][d] = acc[w];
}

// ---------------- logits[t,q,w] = sum_d query[t,q,d] * W[t,w,d] ----------------
#define QT 10
__global__ __launch_bounds__(256) void logits_kernel(const float* __restrict__ query,
                                                     float* __restrict__ out) {
    int t = blockIdx.y;
    int q0 = blockIdx.x * QT;
    int tid = threadIdx.x;
    float acc[QT][NW];
#pragma unroll
    for (int q = 0; q < QT; q++)
#pragma unroll
        for (int w = 0; w < NW; w++) acc[q][w] = 0.f;
    const float* Qp = query + ((size_t)t * NQ + q0) * DD;
    for (int d = tid; d < DD; d += 256) {
        float wv[NW];
#pragma unroll
        for (int w = 0; w < NW; w++) wv[w] = g_W[t][w][d];
#pragma unroll
        for (int q = 0; q < QT; q++) {
            float qv = Qp[(size_t)q * DD + d];
#pragma unroll
            for (int w = 0; w < NW; w++) acc[q][w] += qv * wv[w];
        }
    }
#pragma unroll
    for (int q = 0; q < QT; q++)
#pragma unroll
        for (int w = 0; w < NW; w++)
#pragma unroll
            for (int o = 16; o > 0; o >>= 1)
                acc[q][w] += __shfl_down_sync(0xffffffffu, acc[q][w], o);
    __shared__ float part[8][QT * NW];
    int lane = tid & 31, warp = tid >> 5;
    if (lane == 0) {
#pragma unroll
        for (int q = 0; q < QT; q++)
#pragma unroll
            for (int w = 0; w < NW; w++) part[warp][q * NW + w] = acc[q][w];
    }
    __syncthreads();
    if (tid < QT * NW) {
        float v = 0.f;
#pragma unroll
        for (int wp = 0; wp < 8; wp++) v += part[wp][tid];
        int q = tid / NW, w = tid % NW;
        out[((size_t)t * NQ + q0 + q) * NW + w] = v;
    }
}

// ---------------- host ----------------
extern "C" void kernel_launch(void* const* d_in, const int* in_sizes, int n_in,
                              void* d_out, int out_size) {
    const float* query  = (const float*)d_in[0];
    const float* sup    = (const float*)d_in[1];
    const int*   labels = (const int*)d_in[2];
    (void)in_sizes; (void)n_in; (void)out_size;

    gram_kernel<<<dim3(4, T), 256>>>(sup);
    gram_reduce<<<(T * NS * NS + 255) / 256, 256>>>();
    setup_kernel<<<T, 384>>>(labels);
    for (int it = 0; it < MAXIT; it++) {
        resid_kernel<<<T, 384>>>();
        factor_kernel<<<dim3(NW, T), 256>>>();
        schur_kernel<<<T, 384>>>();
    }
    wproj_kernel<<<dim3(DD / 256, T), 256>>>(sup);
    logits_kernel<<<dim3(NQ / QT, T), 256>>>(query, (float*)d_out);
}

// round 16
// speedup vs baseline: 2.1117x; 2.1117x over previous
#include <cuda_runtime.h>
#include <math.h>

// Problem constants (fixed by setup_inputs)
#define T   64
#define NS  75
#define NW  5
#define NN  375   // NS*NW
#define DD  4096
#define NQ  150
#define PAD 77    // smem row stride (77 mod 32 = 13, coprime -> conflict-free columns)
#define SIGMA_C 0.1f
#define CREG    0.1f
#define MAXIT   15
#define FULLM 0xffffffffu

// ---------------- device scratch (no allocations allowed) ----------------
__device__ float g_K[T][NS][NS];
__device__ float g_Kpart[4][T][NS][NS];
__device__ float g_Minv[T][NW][NS][NS];
__device__ float g_z[T][NN], g_s[T][NN], g_lam[T][NN];
__device__ float g_e[T][NN], g_h[T][NN];
__device__ float g_r1[T][NN], g_Dv[T][NN], g_rs[T][NN], g_u[T][NN];
__device__ float g_nu[T][NS], g_ra[T][NS];
__device__ float g_mu[T];
__device__ float g_W[T][NW][DD];

// ---------------- Gram: K[t] = S_t S_t^T, split-K over 4 chunks ----------------
__global__ __launch_bounds__(256) void gram_kernel(const float* __restrict__ sup) {
    int c = blockIdx.x, t = blockIdx.y;
    int k0base = c * 1024;
    __shared__ float As[16][80];
    int tx = threadIdx.x % 16, ty = threadIdx.x / 16;
    float acc[5][5];
#pragma unroll
    for (int a = 0; a < 5; a++)
#pragma unroll
        for (int b = 0; b < 5; b++) acc[a][b] = 0.f;
    const float* Sp = sup + (size_t)t * NS * DD;
    for (int kt = 0; kt < 64; kt++) {
        int k0 = k0base + kt * 16;
        __syncthreads();
#pragma unroll
        for (int rb = 0; rb < 80; rb += 16) {
            int r = rb + ty;
            As[tx][r] = (r < NS) ? Sp[(size_t)r * DD + k0 + tx] : 0.f;
        }
        __syncthreads();
#pragma unroll
        for (int k = 0; k < 16; k++) {
            float a[5], b[5];
#pragma unroll
            for (int i = 0; i < 5; i++) a[i] = As[k][ty * 5 + i];
#pragma unroll
            for (int j = 0; j < 5; j++) b[j] = As[k][tx * 5 + j];
#pragma unroll
            for (int i = 0; i < 5; i++)
#pragma unroll
                for (int j = 0; j < 5; j++) acc[i][j] += a[i] * b[j];
        }
    }
#pragma unroll
    for (int i = 0; i < 5; i++) {
        int r = ty * 5 + i; if (r >= NS) continue;
#pragma unroll
        for (int j = 0; j < 5; j++) {
            int cc = tx * 5 + j; if (cc >= NS) continue;
            g_Kpart[c][t][r][cc] = acc[i][j];
        }
    }
}

__global__ void gram_reduce() {
    int idx = blockIdx.x * 256 + threadIdx.x;
    if (idx < T * NS * NS) {
        const float* p = (const float*)g_Kpart;
        float v = 0.f;
#pragma unroll
        for (int c = 0; c < 4; c++) v += p[c * T * NS * NS + idx];
        ((float*)g_K)[idx] = v;
    }
}

// ---------------- init state ----------------
__global__ void setup_kernel(const int* __restrict__ labels) {
    int t = blockIdx.x, tid = threadIdx.x;
    if (tid < NN) {
        int i = tid / NW, w = tid % NW;
        float y = (labels[t * NS + i] == w) ? 1.f : 0.f;
        g_e[t][tid] = -y;
        g_h[t][tid] = CREG * y;
        g_z[t][tid] = 0.f;
        g_s[t][tid] = 1.f;
        g_lam[t][tid] = 1.f;
    }
    if (tid < NS) g_nu[t][tid] = 0.f;
}

// ---------------- residuals ----------------
__global__ __launch_bounds__(384) void resid_kernel() {
    int t = blockIdx.x, tid = threadIdx.x;
    __shared__ float Zs[NN];
    __shared__ float red[12];
    __shared__ float smu;
    float z = 0.f, s = 1.f, lam = 1.f, e = 0.f, h = 0.f;
    if (tid < NN) {
        z = g_z[t][tid]; Zs[tid] = z;
        s = g_s[t][tid]; lam = g_lam[t][tid];
        e = g_e[t][tid]; h = g_h[t][tid];
    }
    __syncthreads();
    float ls = (tid < NN) ? lam * s : 0.f;
#pragma unroll
    for (int o = 16; o > 0; o >>= 1) ls += __shfl_down_sync(FULLM, ls, o);
    if ((tid & 31) == 0) red[tid >> 5] = ls;
    __syncthreads();
    if (tid == 0) {
        float sum = 0.f;
        for (int wi = 0; wi < 12; wi++) sum += red[wi];
        smu = sum / (float)NN;
        g_mu[t] = smu;
    }
    __syncthreads();
    float mu = smu;
    if (tid < NN) {
        int i = tid / NW, w = tid - (tid / NW) * NW;
        const float* Krow = &g_K[t][i][0];
        float kz = 0.f;
#pragma unroll 5
        for (int j = 0; j < NS; j++) kz += Krow[j] * Zs[j * NW + w];
        float rz = kz + z + e + lam + g_nu[t][i];
        float rs = z + s - h;
        g_rs[t][tid] = rs;
        g_r1[t][tid] = -rz - (lam * rs - lam * s + SIGMA_C * mu) / s;
        g_Dv[t][tid] = lam / s;
    }
    if (tid < NS) {
        float ra = 0.f;
#pragma unroll
        for (int w = 0; w < NW; w++) ra += Zs[tid * NW + w];
        g_ra[t][tid] = ra;
    }
}

// ---- warp-register 25x25 Cholesky (lane = row), writes lower block + dinv ----
__device__ __forceinline__ void warp_chol25(float (*A)[PAD], float* dinv, int base, int lane) {
    int r = lane < 25 ? lane : 24;
    float row[25];
#pragma unroll
    for (int j = 0; j < 25; j++) row[j] = A[base + r][base + j];
#pragma unroll
    for (int k = 0; k < 25; k++) {
        float dk = __shfl_sync(FULLM, row[k], k);
        float is = rsqrtf(dk);
        is = is * (1.5f - 0.5f * dk * is * is);   // Newton refinement
        float c = row[k] * is;
        if (lane == k) { row[k] = dk * is; dinv[base + k] = is; }
        else if (lane > k) row[k] = c;
#pragma unroll
        for (int j = k + 1; j < 25; j++) {
            float cj = __shfl_sync(FULLM, c, j);
            if (lane > k) row[j] -= c * cj;
        }
    }
    if (lane < 25) {
#pragma unroll
        for (int j = 0; j < 25; j++)
            if (j <= lane) A[base + lane][base + j] = row[j];
    }
}

// ---- blocked 75x75 Cholesky (lower) in smem, 256 threads, ~9 barriers ----
__device__ __forceinline__ void chol75(float (*A)[PAD], float* dinv, int tid) {
    int lane = tid & 31, warp = tid >> 5;
#pragma unroll
    for (int p = 0; p < 3; p++) {
        const int base = p * 25;
        if (warp == 0) warp_chol25(A, dinv, base, lane);
        __syncthreads();
        const int rem = NS - base - 25;
        if (rem > 0) {
            // TRSM: one row per thread, fully unrolled register substitution
            for (int rr = base + 25 + tid; rr < NS; rr += 256) {
                float x[25];
#pragma unroll
                for (int j = 0; j < 25; j++) x[j] = A[rr][base + j];
#pragma unroll
                for (int j = 0; j < 25; j++) {
                    float s = x[j];
#pragma unroll
                    for (int i = 0; i < j; i++) s -= x[i] * A[base + j][base + i];
                    x[j] = s * dinv[base + j];
                }
#pragma unroll
                for (int j = 0; j < 25; j++) A[rr][base + j] = x[j];
            }
            __syncthreads();
            // full-square trailing SYRK (keeps trailing block symmetric)
            const int tot = rem * rem;
            for (int idx = tid; idx < tot; idx += 256) {
                int ii = idx / rem, jj = idx - (idx / rem) * rem;
                int i = base + 25 + ii, j = base + 25 + jj;
                float s = 0.f;
#pragma unroll
                for (int c = 0; c < 25; c++) s += A[i][base + c] * A[j][base + c];
                A[i][j] -= s;
            }
            __syncthreads();
        }
    }
}

// ---- per (task,way): factor, invert (W = L^-1, Minv = W^T W), u = Minv*r1 ----
__global__ __launch_bounds__(256) void factor_kernel() {
    int w = blockIdx.x, t = blockIdx.y, tid = threadIdx.x;
    int lane = tid & 31, warp = tid >> 5;
    __shared__ float M[NS][PAD];
    __shared__ float V[NS][PAD];   // W = L^{-1}, strict upper kept zero
    __shared__ float dinv[NS];
    __shared__ float r1w[NS], w1[NS];
#define TB(a, b) M[a][50 + (b)]   // scratch 25x25 in M's dead upper-right

    for (int idx = tid; idx < NS * PAD; idx += 256) ((float*)V)[idx] = 0.f;
    for (int idx = tid; idx < NS * NS; idx += 256) {
        int i = idx / NS, j = idx - (idx / NS) * NS;
        float v = g_K[t][i][j];
        if (i == j) v += 1.f + g_Dv[t][i * NW + w];
        M[i][j] = v;
    }
    for (int j = tid; j < NS; j += 256) r1w[j] = g_r1[t][j * NW + w];
    __syncthreads();

    chol75(M, dinv, tid);

    // invert diagonal blocks: warp p -> block p, lane = column, fully unrolled
    if (warp < 3 && lane < 25) {
        const int base = warp * 25;
        const int j = lane;
        float x[25];
#pragma unroll
        for (int i = 0; i < 25; i++) {
            float s = (i == j) ? 1.f : 0.f;
#pragma unroll
            for (int k = 0; k < i; k++) s -= M[base + i][base + k] * x[k];
            x[i] = s * dinv[base + i];
        }
#pragma unroll
        for (int i = 0; i < 25; i++)
            if (i >= j) V[base + i][base + j] = x[i];
    }
    __syncthreads();
    // W10 = -W11 * (L10 * W00)
    for (int idx = tid; idx < 625; idx += 256) {
        int a = idx / 25, b = idx - (idx / 25) * 25;
        float s = 0.f;
        for (int d = b; d < 25; d++) s += M[25 + a][d] * V[d][b];
        TB(a, b) = s;
    }
    __syncthreads();
    for (int idx = tid; idx < 625; idx += 256) {
        int a = idx / 25, b = idx - (idx / 25) * 25;
        float s = 0.f;
        for (int c = 0; c <= a; c++) s += V[25 + a][25 + c] * TB(c, b);
        V[25 + a][b] = -s;
    }
    __syncthreads();
    // W21 = -W22 * (L21 * W11)
    for (int idx = tid; idx < 625; idx += 256) {
        int a = idx / 25, b = idx - (idx / 25) * 25;
        float s = 0.f;
        for (int d = b; d < 25; d++) s += M[50 + a][25 + d] * V[25 + d][25 + b];
        TB(a, b) = s;
    }
    __syncthreads();
    for (int idx = tid; idx < 625; idx += 256) {
        int a = idx / 25, b = idx - (idx / 25) * 25;
        float s = 0.f;
        for (int c = 0; c <= a; c++) s += V[50 + a][50 + c] * TB(c, b);
        V[50 + a][25 + b] = -s;
    }
    __syncthreads();
    // W20 = -W22 * (L20 * W00 + L21 * W10)
    for (int idx = tid; idx < 625; idx += 256) {
        int a = idx / 25, b = idx - (idx / 25) * 25;
        float s = 0.f;
        for (int d = b; d < 25; d++) s += M[50 + a][d] * V[d][b];
        for (int d = 0; d < 25; d++) s += M[50 + a][25 + d] * V[25 + d][b];
        TB(a, b) = s;
    }
    __syncthreads();
    for (int idx = tid; idx < 625; idx += 256) {
        int a = idx / 25, b = idx - (idx / 25) * 25;
        float s = 0.f;
        for (int c = 0; c <= a; c++) s += V[50 + a][50 + c] * TB(c, b);
        V[50 + a][b] = -s;
    }
    __syncthreads();

    // u = Minv * r1 = W^T (W r1)
    for (int k = tid; k < NS; k += 256) {
        float s = 0.f;
        for (int c = 0; c <= k; c++) s += V[k][c] * r1w[c];
        w1[k] = s;
    }
    __syncthreads();
    for (int i = tid; i < NS; i += 256) {
        float s = 0.f;
        for (int k = i; k < NS; k++) s += V[k][i] * w1[k];
        g_u[t][i * NW + w] = s;
    }
    // Minv = W^T W (full square; 2-wide j-tiles, padded col 75 is zero)
    for (int idx = tid; idx < NS * 38; idx += 256) {
        int i = idx / 38, jj = idx - (idx / 38) * 38;
        int j0 = jj * 2, j1 = j0 + 1;
        int ks = i > j0 ? i : j0;
        float s0 = 0.f, s1 = 0.f;
        for (int k = ks; k < NS; k++) {
            float vi = V[k][i];
            s0 += vi * V[k][j0];
            s1 += vi * V[k][j1];
        }
        g_Minv[t][w][i][j0] = s0;
        if (j1 < NS) g_Minv[t][w][i][j1] = s1;
    }
#undef TB
}

// ---- per task: Schur solve for dnu (warp-register triangular solves), update ----
__global__ __launch_bounds__(256) void schur_kernel() {
    int t = blockIdx.x, tid = threadIdx.x;
    int lane = tid & 31, warp = tid >> 5;
    __shared__ float S[NS][PAD];
    __shared__ float dinv[NS];
    __shared__ float rhs[NS];
    __shared__ float us[NN];
    __shared__ float red[8];
    __shared__ float salpha;

    for (int idx = tid; idx < NS * NS; idx += 256) {
        int i = idx / NS, j = idx - (idx / NS) * NS;
        float s = 0.f;
#pragma unroll
        for (int w = 0; w < NW; w++) s += g_Minv[t][w][i][j];
        S[i][j] = s;
    }
    for (int idx = tid; idx < NN; idx += 256) us[idx] = g_u[t][idx];
    __syncthreads();
    for (int i = tid; i < NS; i += 256) {
        float acc = g_ra[t][i];
#pragma unroll
        for (int w = 0; w < NW; w++) acc += us[i * NW + w];
        rhs[i] = acc;
    }
    __syncthreads();

    chol75(S, dinv, tid);

    // triangular solves, warp 0, rhs in registers (3 per lane), shfl-only
    if (warp == 0) {
        float x0 = rhs[lane];
        float x1 = rhs[lane + 32];
        float x2 = (lane + 64 < NS) ? rhs[lane + 64] : 0.f;
        // forward: L y = rhs
#pragma unroll
        for (int k = 0; k < NS; k++) {
            const int m = k >> 5, src = k & 31;
            float xk;
            if (m == 0)      { if (lane == src) x0 *= dinv[k]; xk = __shfl_sync(FULLM, x0, src); }
            else if (m == 1) { if (lane == src) x1 *= dinv[k]; xk = __shfl_sync(FULLM, x1, src); }
            else             { if (lane == src) x2 *= dinv[k]; xk = __shfl_sync(FULLM, x2, src); }
            if (m == 0) {
                if (lane > src) x0 -= S[lane][k] * xk;
                x1 -= S[lane + 32][k] * xk;
                if (lane + 64 < NS) x2 -= S[lane + 64][k] * xk;
            } else if (m == 1) {
                if (lane > src) x1 -= S[lane + 32][k] * xk;
                if (lane + 64 < NS) x2 -= S[lane + 64][k] * xk;
            } else {
                if (lane > src && lane + 64 < NS) x2 -= S[lane + 64][k] * xk;
            }
        }
        // backward: L^T dnu = y  (L^T[i][k] = L[k][i])
#pragma unroll
        for (int k = NS - 1; k >= 0; k--) {
            const int m = k >> 5, src = k & 31;
            float xk;
            if (m == 0)      { if (lane == src) x0 *= dinv[k]; xk = __shfl_sync(FULLM, x0, src); }
            else if (m == 1) { if (lane == src) x1 *= dinv[k]; xk = __shfl_sync(FULLM, x1, src); }
            else             { if (lane == src) x2 *= dinv[k]; xk = __shfl_sync(FULLM, x2, src); }
            if (lane < k)       x0 -= S[k][lane] * xk;
            if (lane + 32 < k)  x1 -= S[k][lane + 32] * xk;
            if (lane + 64 < k)  x2 -= S[k][lane + 64] * xk;
        }
        rhs[lane] = x0;
        rhs[lane + 32] = x1;
        if (lane + 64 < NS) rhs[lane + 64] = x2;
    }
    __syncthreads();

    // rhs == dnu. dz = u - Minv*dnu; step length; state update (2 elems/thread)
    float mu = g_mu[t];
    float rat = INFINITY;
    float dz0 = 0.f, ds0 = 0.f, dl0 = 0.f, z0 = 0.f, sv0 = 1.f, lm0 = 1.f;
    float dz1 = 0.f, ds1 = 0.f, dl1 = 0.f, z1 = 0.f, sv1 = 1.f, lm1 = 1.f;
    const int idx0 = tid, idx1 = tid + 256;
    {
        int i = idx0 / NW, w = idx0 - (idx0 / NW) * NW;
        float acc = us[idx0];
        const float* Mi = &g_Minv[t][w][i][0];
#pragma unroll 5
        for (int j = 0; j < NS; j++) acc -= Mi[j] * rhs[j];
        dz0 = acc;
        z0 = g_z[t][idx0]; sv0 = g_s[t][idx0]; lm0 = g_lam[t][idx0];
        float rsv = g_rs[t][idx0];
        ds0 = -rsv - dz0;
        dl0 = (lm0 * dz0 + lm0 * rsv - lm0 * sv0 + SIGMA_C * mu) / sv0;
        float a1 = (ds0 < 0.f) ? (-sv0 / ds0) : INFINITY;
        float a2 = (dl0 < 0.f) ? (-lm0 / dl0) : INFINITY;
        rat = fminf(a1, a2);
    }
    if (idx1 < NN) {
        int i = idx1 / NW, w = idx1 - (idx1 / NW) * NW;
        float acc = us[idx1];
        const float* Mi = &g_Minv[t][w][i][0];
#pragma unroll 5
        for (int j = 0; j < NS; j++) acc -= Mi[j] * rhs[j];
        dz1 = acc;
        z1 = g_z[t][idx1]; sv1 = g_s[t][idx1]; lm1 = g_lam[t][idx1];
        float rsv = g_rs[t][idx1];
        ds1 = -rsv - dz1;
        dl1 = (lm1 * dz1 + lm1 * rsv - lm1 * sv1 + SIGMA_C * mu) / sv1;
        float a1 = (ds1 < 0.f) ? (-sv1 / ds1) : INFINITY;
        float a2 = (dl1 < 0.f) ? (-lm1 / dl1) : INFINITY;
        rat = fminf(rat, fminf(a1, a2));
    }
#pragma unroll
    for (int o = 16; o > 0; o >>= 1) rat = fminf(rat, __shfl_down_sync(FULLM, rat, o));
    if (lane == 0) red[warp] = rat;
    __syncthreads();
    if (tid == 0) {
        float m = red[0];
        for (int wi = 1; wi < 8; wi++) m = fminf(m, red[wi]);
        salpha = fminf(1.f, 0.99f * m);
    }
    __syncthreads();
    float alpha = salpha;
    g_z[t][idx0]   = z0  + alpha * dz0;
    g_s[t][idx0]   = sv0 + alpha * ds0;
    g_lam[t][idx0] = lm0 + alpha * dl0;
    if (idx1 < NN) {
        g_z[t][idx1]   = z1  + alpha * dz1;
        g_s[t][idx1]   = sv1 + alpha * ds1;
        g_lam[t][idx1] = lm1 + alpha * dl1;
    }
    for (int i = tid; i < NS; i += 256) g_nu[t][i] += alpha * rhs[i];
}

// ---------------- W[t,w,d] = sum_n sup[t,n,d] * z[t,n*NW+w] ----------------
__global__ __launch_bounds__(256) void wproj_kernel(const float* __restrict__ sup) {
    int t = blockIdx.y;
    int d = blockIdx.x * 256 + threadIdx.x;
    __shared__ float zs[NN];
    for (int idx = threadIdx.x; idx < NN; idx += 256) zs[idx] = g_z[t][idx];
    __syncthreads();
    float acc[NW] = {0.f, 0.f, 0.f, 0.f, 0.f};
    const float* Sp = sup + (size_t)t * NS * DD + d;
    for (int n = 0; n < NS; n++) {
        float sv = Sp[(size_t)n * DD];
#pragma unroll
        for (int w = 0; w < NW; w++) acc[w] += sv * zs[n * NW + w];
    }
#pragma unroll
    for (int w = 0; w < NW; w++) g_W[t][w][d] = acc[w];
}

// ---------------- logits[t,q,w] = sum_d query[t,q,d] * W[t,w,d] ----------------
#define QT 10
__global__ __launch_bounds__(256) void logits_kernel(const float* __restrict__ query,
                                                     float* __restrict__ out) {
    int t = blockIdx.y;
    int q0 = blockIdx.x * QT;
    int tid = threadIdx.x;
    float acc[QT][NW];
#pragma unroll
    for (int q = 0; q < QT; q++)
#pragma unroll
        for (int w = 0; w < NW; w++) acc[q][w] = 0.f;
    const float* Qp = query + ((size_t)t * NQ + q0) * DD;
    for (int d = tid; d < DD; d += 256) {
        float wv[NW];
#pragma unroll
        for (int w = 0; w < NW; w++) wv[w] = g_W[t][w][d];
#pragma unroll
        for (int q = 0; q < QT; q++) {
            float qv = Qp[(size_t)q * DD + d];
#pragma unroll
            for (int w = 0; w < NW; w++) acc[q][w] += qv * wv[w];
        }
    }
#pragma unroll
    for (int q = 0; q < QT; q++)
#pragma unroll
        for (int w = 0; w < NW; w++)
#pragma unroll
            for (int o = 16; o > 0; o >>= 1)
                acc[q][w] += __shfl_down_sync(FULLM, acc[q][w], o);
    __shared__ float part[8][QT * NW];
    int lane = tid & 31, warp = tid >> 5;
    if (lane == 0) {
#pragma unroll
        for (int q = 0; q < QT; q++)
#pragma unroll
            for (int w = 0; w < NW; w++) part[warp][q * NW + w] = acc[q][w];
    }
    __syncthreads();
    if (tid < QT * NW) {
        float v = 0.f;
#pragma unroll
        for (int wp = 0; wp < 8; wp++) v += part[wp][tid];
        int q = tid / NW, w = tid % NW;
        out[((size_t)t * NQ + q0 + q) * NW + w] = v;
    }
}

// ---------------- host ----------------
extern "C" void kernel_launch(void* const* d_in, const int* in_sizes, int n_in,
                              void* d_out, int out_size) {
    const float* query  = (const float*)d_in[0];
    const float* sup    = (const float*)d_in[1];
    const int*   labels = (const int*)d_in[2];
    (void)in_sizes; (void)n_in; (void)out_size;

    gram_kernel<<<dim3(4, T), 256>>>(sup);
    gram_reduce<<<(T * NS * NS + 255) / 256, 256>>>();
    setup_kernel<<<T, 384>>>(labels);
    for (int it = 0; it < MAXIT; it++) {
        resid_kernel<<<T, 384>>>();
        factor_kernel<<<dim3(NW, T), 256>>>();
        schur_kernel<<<T, 256>>>();
    }
    wproj_kernel<<<dim3(DD / 256, T), 256>>>(sup);
    logits_kernel<<<dim3(NQ / QT, T), 256>>>(query, (float*)d_out);
}

// round 17
// speedup vs baseline: 2.1164x; 1.0022x over previous
#include <cuda_runtime.h>
#include <math.h>

// Problem constants (fixed by setup_inputs)
#define T   64
#define NS  75
#define NW  5
#define NN  375   // NS*NW
#define DD  4096
#define NQ  150
#define PAD 77    // smem row stride (77 mod 32 = 13, coprime -> conflict-free columns)
#define SIGMA_C 0.1f
#define CREG    0.1f
#define MAXIT   15
#define FULLM 0xffffffffu

// ---------------- device scratch (no allocations allowed) ----------------
__device__ float g_K[T][NS][NS];
__device__ float g_Kpart[4][T][NS][NS];
__device__ float g_Minv[T][NW][NS][NS];
__device__ float g_z[T][NN], g_s[T][NN], g_lam[T][NN];
__device__ float g_e[T][NN], g_h[T][NN];
__device__ float g_r1[T][NN], g_Dv[T][NN], g_rs[T][NN], g_u[T][NN];
__device__ float g_nu[T][NS], g_ra[T][NS];
__device__ float g_mu[T];
__device__ float g_W[T][NW][DD];

// ---------------- Gram: K[t] = S_t S_t^T, split-K over 4 chunks ----------------
__global__ __launch_bounds__(256) void gram_kernel(const float* __restrict__ sup) {
    int c = blockIdx.x, t = blockIdx.y;
    int k0base = c * 1024;
    __shared__ float As[16][80];
    int tx = threadIdx.x % 16, ty = threadIdx.x / 16;
    float acc[5][5];
#pragma unroll
    for (int a = 0; a < 5; a++)
#pragma unroll
        for (int b = 0; b < 5; b++) acc[a][b] = 0.f;
    const float* Sp = sup + (size_t)t * NS * DD;
    for (int kt = 0; kt < 64; kt++) {
        int k0 = k0base + kt * 16;
        __syncthreads();
#pragma unroll
        for (int rb = 0; rb < 80; rb += 16) {
            int r = rb + ty;
            As[tx][r] = (r < NS) ? Sp[(size_t)r * DD + k0 + tx] : 0.f;
        }
        __syncthreads();
#pragma unroll
        for (int k = 0; k < 16; k++) {
            float a[5], b[5];
#pragma unroll
            for (int i = 0; i < 5; i++) a[i] = As[k][ty * 5 + i];
#pragma unroll
            for (int j = 0; j < 5; j++) b[j] = As[k][tx * 5 + j];
#pragma unroll
            for (int i = 0; i < 5; i++)
#pragma unroll
                for (int j = 0; j < 5; j++) acc[i][j] += a[i] * b[j];
        }
    }
#pragma unroll
    for (int i = 0; i < 5; i++) {
        int r = ty * 5 + i; if (r >= NS) continue;
#pragma unroll
        for (int j = 0; j < 5; j++) {
            int cc = tx * 5 + j; if (cc >= NS) continue;
            g_Kpart[c][t][r][cc] = acc[i][j];
        }
    }
}

__global__ void gram_reduce() {
    int idx = blockIdx.x * 256 + threadIdx.x;
    if (idx < T * NS * NS) {
        const float* p = (const float*)g_Kpart;
        float v = 0.f;
#pragma unroll
        for (int c = 0; c < 4; c++) v += p[c * T * NS * NS + idx];
        ((float*)g_K)[idx] = v;
    }
}

// ---------------- init state ----------------
__global__ void setup_kernel(const int* __restrict__ labels) {
    int t = blockIdx.x, tid = threadIdx.x;
    if (tid < NN) {
        int i = tid / NW, w = tid % NW;
        float y = (labels[t * NS + i] == w) ? 1.f : 0.f;
        g_e[t][tid] = -y;
        g_h[t][tid] = CREG * y;
        g_z[t][tid] = 0.f;
        g_s[t][tid] = 1.f;
        g_lam[t][tid] = 1.f;
    }
    if (tid < NS) g_nu[t][tid] = 0.f;
}

// ---------------- residuals ----------------
__global__ __launch_bounds__(384) void resid_kernel() {
    int t = blockIdx.x, tid = threadIdx.x;
    __shared__ float Zs[NN];
    __shared__ float red[12];
    __shared__ float smu;
    float z = 0.f, s = 1.f, lam = 1.f, e = 0.f, h = 0.f;
    if (tid < NN) {
        z = g_z[t][tid]; Zs[tid] = z;
        s = g_s[t][tid]; lam = g_lam[t][tid];
        e = g_e[t][tid]; h = g_h[t][tid];
    }
    __syncthreads();
    float ls = (tid < NN) ? lam * s : 0.f;
#pragma unroll
    for (int o = 16; o > 0; o >>= 1) ls += __shfl_down_sync(FULLM, ls, o);
    if ((tid & 31) == 0) red[tid >> 5] = ls;
    __syncthreads();
    if (tid == 0) {
        float sum = 0.f;
        for (int wi = 0; wi < 12; wi++) sum += red[wi];
        smu = sum / (float)NN;
        g_mu[t] = smu;
    }
    __syncthreads();
    float mu = smu;
    if (tid < NN) {
        int i = tid / NW, w = tid - (tid / NW) * NW;
        const float* Krow = &g_K[t][i][0];
        float kz = 0.f;
#pragma unroll 5
        for (int j = 0; j < NS; j++) kz += Krow[j] * Zs[j * NW + w];
        float rz = kz + z + e + lam + g_nu[t][i];
        float rs = z + s - h;
        g_rs[t][tid] = rs;
        g_r1[t][tid] = -rz - (lam * rs - lam * s + SIGMA_C * mu) / s;
        g_Dv[t][tid] = lam / s;
    }
    if (tid < NS) {
        float ra = 0.f;
#pragma unroll
        for (int w = 0; w < NW; w++) ra += Zs[tid * NW + w];
        g_ra[t][tid] = ra;
    }
}

// ---- warp-register 25x25 Cholesky (lane = row), writes lower block + dinv ----
__device__ __forceinline__ void warp_chol25(float (*A)[PAD], float* dinv, int base, int lane) {
    int r = lane < 25 ? lane : 24;
    float row[25];
#pragma unroll
    for (int j = 0; j < 25; j++) row[j] = A[base + r][base + j];
#pragma unroll
    for (int k = 0; k < 25; k++) {
        float dk = __shfl_sync(FULLM, row[k], k);
        float is = rsqrtf(dk);
        is = is * (1.5f - 0.5f * dk * is * is);   // Newton refinement
        float c = row[k] * is;
        if (lane == k) { row[k] = dk * is; dinv[base + k] = is; }
        else if (lane > k) row[k] = c;
#pragma unroll
        for (int j = k + 1; j < 25; j++) {
            float cj = __shfl_sync(FULLM, c, j);
            if (lane > k) row[j] -= c * cj;
        }
    }
    if (lane < 25) {
#pragma unroll
        for (int j = 0; j < 25; j++)
            if (j <= lane) A[base + lane][base + j] = row[j];
    }
}

// ---- blocked 75x75 Cholesky (lower) in smem, 256 threads, ~9 barriers ----
__device__ __forceinline__ void chol75(float (*A)[PAD], float* dinv, int tid) {
    int lane = tid & 31, warp = tid >> 5;
#pragma unroll
    for (int p = 0; p < 3; p++) {
        const int base = p * 25;
        if (warp == 0) warp_chol25(A, dinv, base, lane);
        __syncthreads();
        const int rem = NS - base - 25;
        if (rem > 0) {
            // TRSM: one row per thread, fully unrolled register substitution
            for (int rr = base + 25 + tid; rr < NS; rr += 256) {
                float x[25];
#pragma unroll
                for (int j = 0; j < 25; j++) x[j] = A[rr][base + j];
#pragma unroll
                for (int j = 0; j < 25; j++) {
                    float s = x[j];
#pragma unroll
                    for (int i = 0; i < j; i++) s -= x[i] * A[base + j][base + i];
                    x[j] = s * dinv[base + j];
                }
#pragma unroll
                for (int j = 0; j < 25; j++) A[rr][base + j] = x[j];
            }
            __syncthreads();
            // full-square trailing SYRK (keeps trailing block symmetric)
            const int tot = rem * rem;
            for (int idx = tid; idx < tot; idx += 256) {
                int ii = idx / rem, jj = idx - (idx / rem) * rem;
                int i = base + 25 + ii, j = base + 25 + jj;
                float s = 0.f;
#pragma unroll
                for (int c = 0; c < 25; c++) s += A[i][base + c] * A[j][base + c];
                A[i][j] -= s;
            }
            __syncthreads();
        }
    }
}

// ---- per (task,way): factor, invert (W = L^-1, Minv = W^T W), u = Minv*r1 ----
__global__ __launch_bounds__(256) void factor_kernel() {
    int w = blockIdx.x, t = blockIdx.y, tid = threadIdx.x;
    int lane = tid & 31, warp = tid >> 5;
    __shared__ float M[NS][PAD];
    __shared__ float V[NS][PAD];   // W = L^{-1}, strict upper kept zero
    __shared__ float dinv[NS];
    __shared__ float r1w[NS], w1[NS];
#define TB(a, b) M[a][50 + (b)]   // scratch 25x25 in M's dead upper-right

    for (int idx = tid; idx < NS * PAD; idx += 256) ((float*)V)[idx] = 0.f;
    for (int idx = tid; idx < NS * NS; idx += 256) {
        int i = idx / NS, j = idx - (idx / NS) * NS;
        float v = g_K[t][i][j];
        if (i == j) v += 1.f + g_Dv[t][i * NW + w];
        M[i][j] = v;
    }
    for (int j = tid; j < NS; j += 256) r1w[j] = g_r1[t][j * NW + w];
    __syncthreads();

    chol75(M, dinv, tid);

    // invert diagonal blocks: warp p -> block p, lane = column, fully unrolled
    if (warp < 3 && lane < 25) {
        const int base = warp * 25;
        const int j = lane;
        float x[25];
#pragma unroll
        for (int i = 0; i < 25; i++) {
            float s = (i == j) ? 1.f : 0.f;
#pragma unroll
            for (int k = 0; k < i; k++) s -= M[base + i][base + k] * x[k];
            x[i] = s * dinv[base + i];
        }
#pragma unroll
        for (int i = 0; i < 25; i++)
            if (i >= j) V[base + i][base + j] = x[i];
    }
    __syncthreads();
    // W10 = -W11 * (L10 * W00)
    for (int idx = tid; idx < 625; idx += 256) {
        int a = idx / 25, b = idx - (idx / 25) * 25;
        float s = 0.f;
        for (int d = b; d < 25; d++) s += M[25 + a][d] * V[d][b];
        TB(a, b) = s;
    }
    __syncthreads();
    for (int idx = tid; idx < 625; idx += 256) {
        int a = idx / 25, b = idx - (idx / 25) * 25;
        float s = 0.f;
        for (int c = 0; c <= a; c++) s += V[25 + a][25 + c] * TB(c, b);
        V[25 + a][b] = -s;
    }
    __syncthreads();
    // W21 = -W22 * (L21 * W11)
    for (int idx = tid; idx < 625; idx += 256) {
        int a = idx / 25, b = idx - (idx / 25) * 25;
        float s = 0.f;
        for (int d = b; d < 25; d++) s += M[50 + a][25 + d] * V[25 + d][25 + b];
        TB(a, b) = s;
    }
    __syncthreads();
    for (int idx = tid; idx < 625; idx += 256) {
        int a = idx / 25, b = idx - (idx / 25) * 25;
        float s = 0.f;
        for (int c = 0; c <= a; c++) s += V[50 + a][50 + c] * TB(c, b);
        V[50 + a][25 + b] = -s;
    }
    __syncthreads();
    // W20 = -W22 * (L20 * W00 + L21 * W10)
    for (int idx = tid; idx < 625; idx += 256) {
        int a = idx / 25, b = idx - (idx / 25) * 25;
        float s = 0.f;
        for (int d = b; d < 25; d++) s += M[50 + a][d] * V[d][b];
        for (int d = 0; d < 25; d++) s += M[50 + a][25 + d] * V[25 + d][b];
        TB(a, b) = s;
    }
    __syncthreads();
    for (int idx = tid; idx < 625; idx += 256) {
        int a = idx / 25, b = idx - (idx / 25) * 25;
        float s = 0.f;
        for (int c = 0; c <= a; c++) s += V[50 + a][50 + c] * TB(c, b);
        V[50 + a][b] = -s;
    }
    __syncthreads();

    // u = Minv * r1 = W^T (W r1)
    for (int k = tid; k < NS; k += 256) {
        float s = 0.f;
        for (int c = 0; c <= k; c++) s += V[k][c] * r1w[c];
        w1[k] = s;
    }
    __syncthreads();
    for (int i = tid; i < NS; i += 256) {
        float s = 0.f;
        for (int k = i; k < NS; k++) s += V[k][i] * w1[k];
        g_u[t][i * NW + w] = s;
    }
    // Minv = W^T W (full square; 2-wide j-tiles, padded col 75 is zero)
    for (int idx = tid; idx < NS * 38; idx += 256) {
        int i = idx / 38, jj = idx - (idx / 38) * 38;
        int j0 = jj * 2, j1 = j0 + 1;
        int ks = i > j0 ? i : j0;
        float s0 = 0.f, s1 = 0.f;
        for (int k = ks; k < NS; k++) {
            float vi = V[k][i];
            s0 += vi * V[k][j0];
            s1 += vi * V[k][j1];
        }
        g_Minv[t][w][i][j0] = s0;
        if (j1 < NS) g_Minv[t][w][i][j1] = s1;
    }
#undef TB
}

// ---- per task: Schur solve for dnu (warp-register triangular solves), update ----
__global__ __launch_bounds__(256) void schur_kernel() {
    int t = blockIdx.x, tid = threadIdx.x;
    int lane = tid & 31, warp = tid >> 5;
    __shared__ float S[NS][PAD];
    __shared__ float dinv[NS];
    __shared__ float rhs[NS];
    __shared__ float us[NN];
    __shared__ float red[8];
    __shared__ float salpha;

    for (int idx = tid; idx < NS * NS; idx += 256) {
        int i = idx / NS, j = idx - (idx / NS) * NS;
        float s = 0.f;
#pragma unroll
        for (int w = 0; w < NW; w++) s += g_Minv[t][w][i][j];
        S[i][j] = s;
    }
    for (int idx = tid; idx < NN; idx += 256) us[idx] = g_u[t][idx];
    __syncthreads();
    for (int i = tid; i < NS; i += 256) {
        float acc = g_ra[t][i];
#pragma unroll
        for (int w = 0; w < NW; w++) acc += us[i * NW + w];
        rhs[i] = acc;
    }
    __syncthreads();

    chol75(S, dinv, tid);

    // triangular solves, warp 0, rhs in registers (3 per lane), shfl-only
    if (warp == 0) {
        float x0 = rhs[lane];
        float x1 = rhs[lane + 32];
        float x2 = (lane + 64 < NS) ? rhs[lane + 64] : 0.f;
        // forward: L y = rhs
#pragma unroll
        for (int k = 0; k < NS; k++) {
            const int m = k >> 5, src = k & 31;
            float xk;
            if (m == 0)      { if (lane == src) x0 *= dinv[k]; xk = __shfl_sync(FULLM, x0, src); }
            else if (m == 1) { if (lane == src) x1 *= dinv[k]; xk = __shfl_sync(FULLM, x1, src); }
            else             { if (lane == src) x2 *= dinv[k]; xk = __shfl_sync(FULLM, x2, src); }
            if (m == 0) {
                if (lane > src) x0 -= S[lane][k] * xk;
                x1 -= S[lane + 32][k] * xk;
                if (lane + 64 < NS) x2 -= S[lane + 64][k] * xk;
            } else if (m == 1) {
                if (lane > src) x1 -= S[lane + 32][k] * xk;
                if (lane + 64 < NS) x2 -= S[lane + 64][k] * xk;
            } else {
                if (lane > src && lane + 64 < NS) x2 -= S[lane + 64][k] * xk;
            }
        }
        // backward: L^T dnu = y  (L^T[i][k] = L[k][i])
#pragma unroll
        for (int k = NS - 1; k >= 0; k--) {
            const int m = k >> 5, src = k & 31;
            float xk;
            if (m == 0)      { if (lane == src) x0 *= dinv[k]; xk = __shfl_sync(FULLM, x0, src); }
            else if (m == 1) { if (lane == src) x1 *= dinv[k]; xk = __shfl_sync(FULLM, x1, src); }
            else             { if (lane == src) x2 *= dinv[k]; xk = __shfl_sync(FULLM, x2, src); }
            if (lane < k)       x0 -= S[k][lane] * xk;
            if (lane + 32 < k)  x1 -= S[k][lane + 32] * xk;
            if (lane + 64 < k)  x2 -= S[k][lane + 64] * xk;
        }
        rhs[lane] = x0;
        rhs[lane + 32] = x1;
        if (lane + 64 < NS) rhs[lane + 64] = x2;
    }
    __syncthreads();

    // rhs == dnu. dz = u - Minv*dnu; step length; state update (2 elems/thread)
    float mu = g_mu[t];
    float rat = INFINITY;
    float dz0 = 0.f, ds0 = 0.f, dl0 = 0.f, z0 = 0.f, sv0 = 1.f, lm0 = 1.f;
    float dz1 = 0.f, ds1 = 0.f, dl1 = 0.f, z1 = 0.f, sv1 = 1.f, lm1 = 1.f;
    const int idx0 = tid, idx1 = tid + 256;
    {
        int i = idx0 / NW, w = idx0 - (idx0 / NW) * NW;
        float acc = us[idx0];
        const float* Mi = &g_Minv[t][w][i][0];
#pragma unroll 5
        for (int j = 0; j < NS; j++) acc -= Mi[j] * rhs[j];
        dz0 = acc;
        z0 = g_z[t][idx0]; sv0 = g_s[t][idx0]; lm0 = g_lam[t][idx0];
        float rsv = g_rs[t][idx0];
        ds0 = -rsv - dz0;
        dl0 = (lm0 * dz0 + lm0 * rsv - lm0 * sv0 + SIGMA_C * mu) / sv0;
        float a1 = (ds0 < 0.f) ? (-sv0 / ds0) : INFINITY;
        float a2 = (dl0 < 0.f) ? (-lm0 / dl0) : INFINITY;
        rat = fminf(a1, a2);
    }
    if (idx1 < NN) {
        int i = idx1 / NW, w = idx1 - (idx1 / NW) * NW;
        float acc = us[idx1];
        const float* Mi = &g_Minv[t][w][i][0];
#pragma unroll 5
        for (int j = 0; j < NS; j++) acc -= Mi[j] * rhs[j];
        dz1 = acc;
        z1 = g_z[t][idx1]; sv1 = g_s[t][idx1]; lm1 = g_lam[t][idx1];
        float rsv = g_rs[t][idx1];
        ds1 = -rsv - dz1;
        dl1 = (lm1 * dz1 + lm1 * rsv - lm1 * sv1 + SIGMA_C * mu) / sv1;
        float a1 = (ds1 < 0.f) ? (-sv1 / ds1) : INFINITY;
        float a2 = (dl1 < 0.f) ? (-lm1 / dl1) : INFINITY;
        rat = fminf(rat, fminf(a1, a2));
    }
#pragma unroll
    for (int o = 16; o > 0; o >>= 1) rat = fminf(rat, __shfl_down_sync(FULLM, rat, o));
    if (lane == 0) red[warp] = rat;
    __syncthreads();
    if (tid == 0) {
        float m = red[0];
        for (int wi = 1; wi < 8; wi++) m = fminf(m, red[wi]);
        salpha = fminf(1.f, 0.99f * m);
    }
    __syncthreads();
    float alpha = salpha;
    g_z[t][idx0]   = z0  + alpha * dz0;
    g_s[t][idx0]   = sv0 + alpha * ds0;
    g_lam[t][idx0] = lm0 + alpha * dl0;
    if (idx1 < NN) {
        g_z[t][idx1]   = z1  + alpha * dz1;
        g_s[t][idx1]   = sv1 + alpha * ds1;
        g_lam[t][idx1] = lm1 + alpha * dl1;
    }
    for (int i = tid; i < NS; i += 256) g_nu[t][i] += alpha * rhs[i];
}

// ---------------- W[t,w,d] = sum_n sup[t,n,d] * z[t,n*NW+w] ----------------
__global__ __launch_bounds__(256) void wproj_kernel(const float* __restrict__ sup) {
    int t = blockIdx.y;
    int d = blockIdx.x * 256 + threadIdx.x;
    __shared__ float zs[NN];
    for (int idx = threadIdx.x; idx < NN; idx += 256) zs[idx] = g_z[t][idx];
    __syncthreads();
    float acc[NW] = {0.f, 0.f, 0.f, 0.f, 0.f};
    const float* Sp = sup + (size_t)t * NS * DD + d;
    for (int n = 0; n < NS; n++) {
        float sv = Sp[(size_t)n * DD];
#pragma unroll
        for (int w = 0; w < NW; w++) acc[w] += sv * zs[n * NW + w];
    }
#pragma unroll
    for (int w = 0; w < NW; w++) g_W[t][w][d] = acc[w];
}

// ---------------- logits[t,q,w] = sum_d query[t,q,d] * W[t,w,d] ----------------
#define QT 10
__global__ __launch_bounds__(256) void logits_kernel(const float* __restrict__ query,
                                                     float* __restrict__ out) {
    int t = blockIdx.y;
    int q0 = blockIdx.x * QT;
    int tid = threadIdx.x;
    float acc[QT][NW];
#pragma unroll
    for (int q = 0; q < QT; q++)
#pragma unroll
        for (int w = 0; w < NW; w++) acc[q][w] = 0.f;
    const float* Qp = query + ((size_t)t * NQ + q0) * DD;
    for (int d = tid; d < DD; d += 256) {
        float wv[NW];
#pragma unroll
        for (int w = 0; w < NW; w++) wv[w] = g_W[t][w][d];
#pragma unroll
        for (int q = 0; q < QT; q++) {
            float qv = Qp[(size_t)q * DD + d];
#pragma unroll
            for (int w = 0; w < NW; w++) acc[q][w] += qv * wv[w];
        }
    }
#pragma unroll
    for (int q = 0; q < QT; q++)
#pragma unroll
        for (int w = 0; w < NW; w++)
#pragma unroll
            for (int o = 16; o > 0; o >>= 1)
                acc[q][w] += __shfl_down_sync(FULLM, acc[q][w], o);
    __shared__ float part[8][QT * NW];
    int lane = tid & 31, warp = tid >> 5;
    if (lane == 0) {
#pragma unroll
        for (int q = 0; q < QT; q++)
#pragma unroll
            for (int w = 0; w < NW; w++) part[warp][q * NW + w] = acc[q][w];
    }
    __syncthreads();
    if (tid < QT * NW) {
        float v = 0.f;
#pragma unroll
        for (int wp = 0; wp < 8; wp++) v += part[wp][tid];
        int q = tid / NW, w = tid % NW;
        out[((size_t)t * NQ + q0 + q) * NW + w] = v;
    }
}

// ---------------- host ----------------
extern "C" void kernel_launch(void* const* d_in, const int* in_sizes, int n_in,
                              void* d_out, int out_size) {
    const float* query  = (const float*)d_in[0];
    const float* sup    = (const float*)d_in[1];
    const int*   labels = (const int*)d_in[2];
    (void)in_sizes; (void)n_in; (void)out_size;

    gram_kernel<<<dim3(4, T), 256>>>(sup);
    gram_reduce<<<(T * NS * NS + 255) / 256, 256>>>();
    setup_kernel<<<T, 384>>>(labels);
    for (int it = 0; it < MAXIT; it++) {
        resid_kernel<<<T, 384>>>();
        factor_kernel<<<dim3(NW, T), 256>>>();
        schur_kernel<<<T, 256>>>();
    }
    wproj_kernel<<<dim3(DD / 256, T), 256>>>(sup);
    logits_kernel<<<dim3(NQ / QT, T), 256>>>(query, (float*)d_out);
}